// round 16
// baseline (speedup 1.0000x reference)
#include <cuda_runtime.h>
#include <cuda_fp16.h>
#include <math.h>
#include <cstdint>

#define Bn   8
#define SEQ  1024
#define DM   512
#define HID  256
#define NH   8
#define DH   64
#define MROWS (Bn*SEQ)

// ---------------- scratch (device globals; no allocation) ----------------
__device__ __half g_Qh [MROWS*DM];
__device__ __half g_Kh [MROWS*DM];
__device__ __half g_VVh[MROWS*DM];
__device__ __half g_VCh[MROWS*DM];
__device__ __half g_Hh [MROWS*HID];
__device__ __half g_VDh[MROWS*DM];
__device__ __half g_AOh[MROWS*DM];
__device__ __half g_INh[3*MROWS*DM];            // half copies of query,key_in,value
__device__ float  g_PART[Bn*8*DM];
__device__ float  g_HIDP[Bn*8*HID];
__device__ float  g_CWP[Bn*4*DM];
__device__ __half g_WTh[4*DM*DM + 2*DM*HID];    // transposed half weights
__device__ __half g_WVBh[Bn*DM*DM];             // per-batch channel-scaled Wv

#define WT_Q  0
#define WT_K  (DM*DM)
#define WT_V  (2*DM*DM)
#define WT_O  (3*DM*DM)
#define WT_S1 (4*DM*DM)
#define WT_S2 (4*DM*DM + DM*HID)

// ---------------- helpers ----------------
__device__ __forceinline__ uint32_t f22h2(float lo, float hi) {
    uint32_t u; asm("cvt.rn.f16x2.f32 %0, %1, %2;" : "=r"(u) : "f"(hi), "f"(lo)); return u;
}
__device__ __forceinline__ void mma_f16(float* c, const uint32_t* a, uint32_t b0, uint32_t b1) {
    asm volatile("mma.sync.aligned.m16n8k16.row.col.f32.f16.f16.f32 "
        "{%0,%1,%2,%3}, {%4,%5,%6,%7}, {%8,%9}, {%0,%1,%2,%3};"
        : "+f"(c[0]), "+f"(c[1]), "+f"(c[2]), "+f"(c[3])
        : "r"(a[0]), "r"(a[1]), "r"(a[2]), "r"(a[3]), "r"(b0), "r"(b1));
}
__device__ __forceinline__ void ldsm_x4_t(uint32_t& r0, uint32_t& r1, uint32_t& r2, uint32_t& r3,
                                          uint32_t addr) {
    asm volatile("ldmatrix.sync.aligned.m8n8.x4.trans.shared.b16 {%0,%1,%2,%3}, [%4];"
        : "=r"(r0), "=r"(r1), "=r"(r2), "=r"(r3) : "r"(addr));
}
__device__ __forceinline__ uint32_t smem_u32(const void* p) {
    uint32_t a;
    asm("{ .reg .u64 t; cvta.to.shared.u64 t, %1; cvt.u32.u64 %0, t; }" : "=r"(a) : "l"(p));
    return a;
}
__device__ __forceinline__ void cpa16(uint32_t dst, const void* src) {
    asm volatile("cp.async.cg.shared.global [%0], [%1], 16;" :: "r"(dst), "l"(src));
}
#define CP_COMMIT() asm volatile("cp.async.commit_group;" ::: "memory")
#define CP_WAIT1()  asm volatile("cp.async.wait_group 1;" ::: "memory")
#define CP_WAIT0()  asm volatile("cp.async.wait_group 0;" ::: "memory")

// ---------------- prep_all: weight transpose + input cvt + partial means, ONE launch
__global__ void prep_all(const float* __restrict__ Wq, const float* __restrict__ Wk,
                         const float* __restrict__ Wv, const float* __restrict__ Wo,
                         const float* __restrict__ Ws1, const float* __restrict__ Ws2,
                         const float* __restrict__ query, const float* __restrict__ key_in,
                         const float* __restrict__ value,
                         __half* __restrict__ WT, __half* __restrict__ INh,
                         float* __restrict__ part)
{
    int bid = blockIdx.x;
    int t = threadIdx.x;                  // 256

    if (bid < 1280) {
        const float* in; __half* out; int R, C, tb;
        if      (bid < 256)  { in = Wq;  out = WT + WT_Q;  R = DM; C = DM;  tb = bid; }
        else if (bid < 512)  { in = Wk;  out = WT + WT_K;  R = DM; C = DM;  tb = bid - 256; }
        else if (bid < 768)  { in = Wv;  out = WT + WT_V;  R = DM; C = DM;  tb = bid - 512; }
        else if (bid < 1024) { in = Wo;  out = WT + WT_O;  R = DM; C = DM;  tb = bid - 768; }
        else if (bid < 1152) { in = Ws1; out = WT + WT_S1; R = DM; C = HID; tb = bid - 1024; }
        else                 { in = Ws2; out = WT + WT_S2; R = HID; C = DM; tb = bid - 1152; }
        int tilesX = C >> 5;
        int bx = (tb % tilesX) * 32, by = (tb / tilesX) * 32;
        __shared__ float tile[32][33];
        int tx = t & 31, ty = t >> 5;     // (32, 8)
        #pragma unroll
        for (int i = 0; i < 32; i += 8)
            tile[ty + i][tx] = in[(size_t)(by + ty + i) * C + bx + tx];
        __syncthreads();
        #pragma unroll
        for (int i = 0; i < 32; i += 8)
            out[(size_t)(bx + ty + i) * R + by + tx] = __float2half_rn(tile[tx][ty + i]);
    } else if (bid < 13568) {
        int i  = bid - 1280;
        int y  = i >> 12;                 // 0..2
        int x  = i & 4095;
        const float* src = (y == 0) ? query : (y == 1) ? key_in : value;
        size_t i4 = ((size_t)x * 256 + t) * 4;
        float4 f = *(const float4*)&src[i4];
        uint2 o;
        o.x = f22h2(f.x, f.y);
        o.y = f22h2(f.z, f.w);
        *(uint2*)(INh + (size_t)y * MROWS * DM + i4) = o;
    } else {
        int i = bid - 13568;              // 0..63
        int b = i >> 3, s = i & 7;
        const float* vb = value + ((size_t)b * SEQ + s * 128) * DM;
        #pragma unroll
        for (int d = t; d < DM; d += 256) {
            float acc = 0.f;
            #pragma unroll 8
            for (int n = 0; n < 128; n++) acc += vb[(size_t)n * DM + d];
            part[(b * 8 + s) * DM + d] = acc;
        }
    }
}

// ---------------- channel gate, split-K wide-parallel ----------------
__global__ void gate1_kernel(const float* __restrict__ part, const float* __restrict__ Wc1,
                             float* __restrict__ hidp)
{
    int b = blockIdx.x, sl = blockIdx.y;   // (8, 8)
    int t = threadIdx.x;                   // 256
    __shared__ float ps[64];
    if (t < 64) {
        int d = sl * 64 + t;
        float s = 0.f;
        #pragma unroll
        for (int k = 0; k < 8; k++) s += part[(b * 8 + k) * DM + d];
        ps[t] = s * (1.0f / SEQ);
    }
    __syncthreads();
    float acc = 0.f;
    #pragma unroll
    for (int dd = 0; dd < 64; dd++)
        acc += ps[dd] * Wc1[(sl * 64 + dd) * HID + t];
    hidp[(b * 8 + sl) * HID + t] = acc;
}

__global__ void gate2_kernel(const float* __restrict__ hidp, const float* __restrict__ bc1,
                             const float* __restrict__ Wc2, float* __restrict__ cwp)
{
    int b = blockIdx.x, sl = blockIdx.y;   // (8, 4)
    int t = threadIdx.x;                   // 256
    __shared__ float hs[64];
    if (t < 64) {
        int h = sl * 64 + t;
        float s = bc1[h];
        #pragma unroll
        for (int k = 0; k < 8; k++) s += hidp[(b * 8 + k) * HID + h];
        hs[t] = fmaxf(s, 0.f);
    }
    __syncthreads();
    #pragma unroll
    for (int rep = 0; rep < 2; rep++) {
        int d = rep * 256 + t;
        float acc = 0.f;
        #pragma unroll
        for (int hh = 0; hh < 64; hh++)
            acc += hs[hh] * Wc2[(sl * 64 + hh) * DM + d];
        cwp[(b * 4 + sl) * DM + d] = acc;
    }
}

// ---------------- per-batch scaled Wv (half), sigmoid reduce folded in ----------------
__global__ void scale_wv_kernel(const __half* __restrict__ WTV, const float* __restrict__ cwp,
                                const float* __restrict__ bc2, __half* __restrict__ WVB)
{
    int b = blockIdx.y;
    size_t j0 = ((size_t)blockIdx.x * 256 + threadIdx.x) * 8;
    int k = (int)(j0 & (DM - 1));
    float cw[8];
    #pragma unroll
    for (int i = 0; i < 8; i += 4) {
        float4 s4 = *(const float4*)&bc2[k + i];
        #pragma unroll
        for (int sl = 0; sl < 4; sl++) {
            float4 p = *(const float4*)&cwp[(b * 4 + sl) * DM + k + i];
            s4.x += p.x; s4.y += p.y; s4.z += p.z; s4.w += p.w;
        }
        cw[i]   = 1.f / (1.f + __expf(-s4.x));
        cw[i+1] = 1.f / (1.f + __expf(-s4.y));
        cw[i+2] = 1.f / (1.f + __expf(-s4.z));
        cw[i+3] = 1.f / (1.f + __expf(-s4.w));
    }
    uint4 w = *(const uint4*)&WTV[j0];
    uint32_t r[4];
    const uint32_t* ww = (const uint32_t*)&w;
    #pragma unroll
    for (int i = 0; i < 4; i++) {
        __half2 h = *(__half2*)&ww[i];
        float lo = __low2float(h) * cw[2 * i];
        float hi = __high2float(h) * cw[2 * i + 1];
        r[i] = f22h2(lo, hi);
    }
    *(uint4*)&WVB[(size_t)b * DM * DM + j0] = *(uint4*)r;
}

// ---------------- fp16 mma GEMM, K-chunk 64 halfs, 3-stage cp.async ring
#define PITCHW 36
#define TWRD  (128*PITCHW)
#define STGW  (2*TWRD)
#define NSTG  3
#define SMEM_GEMM (NSTG*STGW*4)        // 110592 B

template<int MODE, bool FLOATOUT, bool QSCALE>
__device__ __forceinline__
void gemm_body(const __half* __restrict__ A, const __half* __restrict__ B,
               const float* __restrict__ bias, void* __restrict__ Cv,
               int Kd, int Nd,
               const __half* __restrict__ E1, const __half* __restrict__ E2,
               int m0, int n0)
{
    extern __shared__ __align__(16) uint32_t usm[];
    const uint32_t sb = smem_u32(usm);
    const int t    = threadIdx.x;
    const int lane = t & 31;
    const int wid  = t >> 5;
    const int g    = lane >> 2;
    const int tg   = lane & 3;
    const int wm   = wid & 3;
    const int wn   = wid >> 2;
    const int NK   = Kd / 64;

    float acc[2][8][4];
    #pragma unroll
    for (int mt = 0; mt < 2; mt++)
        #pragma unroll
        for (int nt = 0; nt < 8; nt++)
            #pragma unroll
            for (int j = 0; j < 4; j++) acc[mt][nt][j] = 0.f;

    auto issue = [&](int kc) {
        if (kc < NK) {
            const int k0 = kc * 64;
            const uint32_t ab = sb + (kc % NSTG) * (STGW * 4);
            #pragma unroll
            for (int i = 0; i < 4; i++) {
                int idx = t + i * 256;
                int row = idx >> 3, q = idx & 7;
                uint32_t soff = (row * PITCHW + q * 4) * 4;
                cpa16(ab + soff,              &A[(size_t)(m0 + row) * Kd + k0 + q * 8]);
                cpa16(ab + TWRD * 4 + soff,   &B[(size_t)(n0 + row) * Kd + k0 + q * 8]);
            }
        }
        CP_COMMIT();
    };

    issue(0); issue(1);

    for (int kc = 0; kc < NK; kc++) {
        CP_WAIT1();
        __syncthreads();
        issue(kc + 2);

        const uint32_t* Aw = usm + (kc % NSTG) * STGW;
        const uint32_t* Bw = Aw + TWRD;
        #pragma unroll
        for (int ks = 0; ks < 4; ks++) {
            const int c0 = ks * 8 + tg;
            uint32_t af[2][4];
            #pragma unroll
            for (int mt = 0; mt < 2; mt++) {
                int r0 = wm * 32 + mt * 16 + g;
                af[mt][0] = Aw[r0 * PITCHW + c0];
                af[mt][1] = Aw[(r0 + 8) * PITCHW + c0];
                af[mt][2] = Aw[r0 * PITCHW + c0 + 4];
                af[mt][3] = Aw[(r0 + 8) * PITCHW + c0 + 4];
            }
            #pragma unroll
            for (int nt = 0; nt < 8; nt++) {
                int nn = wn * 64 + nt * 8 + g;
                uint32_t b0 = Bw[nn * PITCHW + c0];
                uint32_t b1 = Bw[nn * PITCHW + c0 + 4];
                mma_f16(acc[0][nt], af[0], b0, b1);
                mma_f16(acc[1][nt], af[1], b0, b1);
            }
        }
    }

    #pragma unroll
    for (int mt = 0; mt < 2; mt++) {
        int r_lo = m0 + wm * 32 + mt * 16 + g;
        int r_hi = r_lo + 8;
        #pragma unroll
        for (int nt = 0; nt < 8; nt++) {
            int col = n0 + wn * 64 + nt * 8 + 2 * tg;
            float bx = bias[col], by = bias[col + 1];
            float v0 = acc[mt][nt][0] + bx;
            float v1 = acc[mt][nt][1] + by;
            float v2 = acc[mt][nt][2] + bx;
            float v3 = acc[mt][nt][3] + by;
            if (MODE == 2) {
                v0 = fmaxf(v0, 0.f); v1 = fmaxf(v1, 0.f);
                v2 = fmaxf(v2, 0.f); v3 = fmaxf(v3, 0.f);
            }
            if (MODE == 3) {
                size_t i_lo = (size_t)r_lo * Nd + col;
                size_t i_hi = (size_t)r_hi * Nd + col;
                float2 e1l = __half22float2(*(const __half2*)&E1[i_lo]);
                float2 e2l = __half22float2(*(const __half2*)&E2[i_lo]);
                float2 e1h = __half22float2(*(const __half2*)&E1[i_hi]);
                float2 e2h = __half22float2(*(const __half2*)&E2[i_hi]);
                v0 = e1l.x / (1.f + __expf(-v0)) + e2l.x;
                v1 = e1l.y / (1.f + __expf(-v1)) + e2l.y;
                v2 = e1h.x / (1.f + __expf(-v2)) + e2h.x;
                v3 = e1h.y / (1.f + __expf(-v3)) + e2h.y;
            }
            if (QSCALE) { v0 *= 0.125f; v1 *= 0.125f; v2 *= 0.125f; v3 *= 0.125f; }
            if (FLOATOUT) {
                float* C = (float*)Cv;
                *(float2*)&C[(size_t)r_lo * Nd + col] = make_float2(v0, v1);
                *(float2*)&C[(size_t)r_hi * Nd + col] = make_float2(v2, v3);
            } else {
                __half* C = (__half*)Cv;
                *(uint32_t*)&C[(size_t)r_lo * Nd + col] = f22h2(v0, v1);
                *(uint32_t*)&C[(size_t)r_hi * Nd + col] = f22h2(v2, v3);
            }
        }
    }
}

template<int MODE, bool FLOATOUT>
__global__ __launch_bounds__(256, 2)
void tgemm(const __half* __restrict__ A, const __half* __restrict__ B,
           const float* __restrict__ bias, void* __restrict__ C,
           int Kd, int Nd,
           const __half* __restrict__ E1, const __half* __restrict__ E2)
{
    gemm_body<MODE, FLOATOUT, false>(A, B, bias, C, Kd, Nd, E1, E2,
                                     blockIdx.y * 128, blockIdx.x * 128);
}

// Q/K/VV projections (Q pre-scaled by 0.125); VC split off for stream overlap
__global__ __launch_bounds__(256, 2)
void proj3(const __half* __restrict__ INh, const __half* __restrict__ WTb,
           const float* __restrict__ bq, const float* __restrict__ bk,
           const float* __restrict__ bv,
           __half* __restrict__ oQ, __half* __restrict__ oK,
           __half* __restrict__ oVV)
{
    const int z = blockIdx.z;
    const int m0 = blockIdx.y * 128, n0 = blockIdx.x * 128;
    const __half* qh = INh;
    const __half* kh = INh + (size_t)MROWS * DM;
    const __half* vh = INh + (size_t)2 * MROWS * DM;
    if (z == 0)
        gemm_body<0, false, true >(qh, WTb + WT_Q, bq, oQ,  DM, DM, nullptr, nullptr, m0, n0);
    else if (z == 1)
        gemm_body<0, false, false>(kh, WTb + WT_K, bk, oK,  DM, DM, nullptr, nullptr, m0, n0);
    else
        gemm_body<0, false, false>(vh, WTb + WT_V, bv, oVV, DM, DM, nullptr, nullptr, m0, n0);
}

__global__ __launch_bounds__(256, 2)
void projVC(const __half* __restrict__ INh, const __half* __restrict__ WVB,
            const float* __restrict__ bv, __half* __restrict__ oVC)
{
    const int m0 = blockIdx.y * 128, n0 = blockIdx.x * 128;
    const int bb = blockIdx.y >> 3;
    const __half* vh = INh + (size_t)2 * MROWS * DM;
    gemm_body<0, false, false>(vh, WVB + (size_t)bb * DM * DM, bv, oVC, DM, DM,
                               nullptr, nullptr, m0, n0);
}

// ---------------- flash attention: fp16 mma, 256-query CTAs (warp owns 32 q)
#define KVPW   36
#define KVTOK  64
#define ASTGW  (2*KVTOK*KVPW)           // 4608 words per stage (K+V)
#define SMEM_ATTN (2*ASTGW*4)           // 36864 B

__global__ __launch_bounds__(256, 1)
void attn_kernel(const __half* __restrict__ Q, const __half* __restrict__ Kp,
                 const __half* __restrict__ V, __half* __restrict__ O)
{
    extern __shared__ __align__(16) uint32_t usm[];
    const uint32_t sb = smem_u32(usm);

    const int qt = blockIdx.x;           // 4 tiles of 256 queries
    const int h  = blockIdx.y;
    const int b  = blockIdx.z;
    const int t  = threadIdx.x;
    const int lane = t & 31;
    const int wid  = t >> 5;
    const int g  = lane >> 2;
    const int tg = lane & 3;
    const int q0 = qt * 256 + wid * 32;  // warp owns 32 queries (2 x m16)

    uint32_t aq[2][4][4];
    #pragma unroll
    for (int mt = 0; mt < 2; mt++) {
        const __half* Qb = Q + ((size_t)(b * SEQ + q0 + mt * 16)) * DM + h * DH;
        #pragma unroll
        for (int ks = 0; ks < 4; ks++) {
            int c0 = ks * 16 + 2 * tg;
            aq[mt][ks][0] = *(const uint32_t*)&Qb[(size_t)g * DM + c0];
            aq[mt][ks][1] = *(const uint32_t*)&Qb[(size_t)(g + 8) * DM + c0];
            aq[mt][ks][2] = *(const uint32_t*)&Qb[(size_t)g * DM + c0 + 8];
            aq[mt][ks][3] = *(const uint32_t*)&Qb[(size_t)(g + 8) * DM + c0 + 8];
        }
    }

    float o[2][8][4];
    #pragma unroll
    for (int mt = 0; mt < 2; mt++)
        #pragma unroll
        for (int nt = 0; nt < 8; nt++)
            #pragma unroll
            for (int j = 0; j < 4; j++) o[mt][nt][j] = 0.f;
    float m_lo[2] = {-1e30f, -1e30f}, m_hi[2] = {-1e30f, -1e30f};
    float l_lo[2] = {0.f, 0.f},       l_hi[2] = {0.f, 0.f};

    const int keyoff = lane & 15;
    const int ncoff  = ((lane >> 4) & 1) * 8;

    auto issue = [&](int kt) {
        if (kt < SEQ / KVTOK) {
            const uint32_t ab = sb + (kt & 1) * (ASTGW * 4);
            #pragma unroll
            for (int i = 0; i < 2; i++) {
                int idx = t + i * 256;
                int tok = idx >> 3, q = idx & 7;
                size_t gaddr = ((size_t)(b * SEQ + kt * KVTOK + tok)) * DM + h * DH + q * 8;
                cpa16(ab + (tok * KVPW + q * 4) * 4, &Kp[gaddr]);
                cpa16(ab + (KVTOK * KVPW + tok * KVPW + q * 4) * 4, &V[gaddr]);
            }
        }
        CP_COMMIT();
    };

    issue(0);

    for (int kt = 0; kt < SEQ / KVTOK; kt++) {
        CP_WAIT0();
        __syncthreads();
        issue(kt + 1);

        const uint32_t* Ks = usm + (kt & 1) * ASTGW;
        const uint32_t  vsb = sb + ((kt & 1) * ASTGW + KVTOK * KVPW) * 4;

        float s[2][8][4];
        #pragma unroll
        for (int mt = 0; mt < 2; mt++)
            #pragma unroll
            for (int nt = 0; nt < 8; nt++)
                #pragma unroll
                for (int j = 0; j < 4; j++) s[mt][nt][j] = 0.f;
        #pragma unroll
        for (int ks = 0; ks < 4; ks++) {
            const int c0 = ks * 8 + tg;
            #pragma unroll
            for (int nt = 0; nt < 8; nt++) {
                int key = nt * 8 + g;
                uint32_t b0 = Ks[key * KVPW + c0];
                uint32_t b1 = Ks[key * KVPW + c0 + 4];
                mma_f16(s[0][nt], aq[0][ks], b0, b1);
                mma_f16(s[1][nt], aq[1][ks], b0, b1);
            }
        }

        #pragma unroll
        for (int mt = 0; mt < 2; mt++) {
            float tl = -1e30f, th = -1e30f;
            #pragma unroll
            for (int nt = 0; nt < 8; nt++) {
                tl = fmaxf(tl, fmaxf(s[mt][nt][0], s[mt][nt][1]));
                th = fmaxf(th, fmaxf(s[mt][nt][2], s[mt][nt][3]));
            }
            tl = fmaxf(tl, __shfl_xor_sync(0xffffffffu, tl, 1));
            tl = fmaxf(tl, __shfl_xor_sync(0xffffffffu, tl, 2));
            th = fmaxf(th, __shfl_xor_sync(0xffffffffu, th, 1));
            th = fmaxf(th, __shfl_xor_sync(0xffffffffu, th, 2));
            float mn_l = fmaxf(m_lo[mt], tl), mn_h = fmaxf(m_hi[mt], th);
            float fl = __expf(m_lo[mt] - mn_l), fh = __expf(m_hi[mt] - mn_h);
            m_lo[mt] = mn_l; m_hi[mt] = mn_h;

            float sl = 0.f, sh = 0.f;
            #pragma unroll
            for (int nt = 0; nt < 8; nt++) {
                s[mt][nt][0] = __expf(s[mt][nt][0] - mn_l);
                s[mt][nt][1] = __expf(s[mt][nt][1] - mn_l);
                s[mt][nt][2] = __expf(s[mt][nt][2] - mn_h);
                s[mt][nt][3] = __expf(s[mt][nt][3] - mn_h);
                sl += s[mt][nt][0] + s[mt][nt][1];
                sh += s[mt][nt][2] + s[mt][nt][3];
            }
            sl += __shfl_xor_sync(0xffffffffu, sl, 1);
            sl += __shfl_xor_sync(0xffffffffu, sl, 2);
            sh += __shfl_xor_sync(0xffffffffu, sh, 1);
            sh += __shfl_xor_sync(0xffffffffu, sh, 2);
            l_lo[mt] = l_lo[mt] * fl + sl;
            l_hi[mt] = l_hi[mt] * fh + sh;
            #pragma unroll
            for (int nt = 0; nt < 8; nt++) {
                o[mt][nt][0] *= fl; o[mt][nt][1] *= fl;
                o[mt][nt][2] *= fh; o[mt][nt][3] *= fh;
            }
        }

        #pragma unroll
        for (int kk = 0; kk < 4; kk++) {
            uint32_t pa0[4], pa1[4];
            pa0[0] = f22h2(s[0][2*kk][0],   s[0][2*kk][1]);
            pa0[1] = f22h2(s[0][2*kk][2],   s[0][2*kk][3]);
            pa0[2] = f22h2(s[0][2*kk+1][0], s[0][2*kk+1][1]);
            pa0[3] = f22h2(s[0][2*kk+1][2], s[0][2*kk+1][3]);
            pa1[0] = f22h2(s[1][2*kk][0],   s[1][2*kk][1]);
            pa1[1] = f22h2(s[1][2*kk][2],   s[1][2*kk][3]);
            pa1[2] = f22h2(s[1][2*kk+1][0], s[1][2*kk+1][1]);
            pa1[3] = f22h2(s[1][2*kk+1][2], s[1][2*kk+1][3]);
            #pragma unroll
            for (int np = 0; np < 4; np++) {
                uint32_t addr = vsb + (uint32_t)((16 * kk + keyoff) * (KVPW * 4)
                                               + (np * 16 + ncoff) * 2);
                uint32_t vb0, vb1, vb2, vb3;
                ldsm_x4_t(vb0, vb1, vb2, vb3, addr);
                mma_f16(o[0][2*np],   pa0, vb0, vb1);
                mma_f16(o[0][2*np+1], pa0, vb2, vb3);
                mma_f16(o[1][2*np],   pa1, vb0, vb1);
                mma_f16(o[1][2*np+1], pa1, vb2, vb3);
            }
        }
    }

    #pragma unroll
    for (int mt = 0; mt < 2; mt++) {
        float inv_lo = 1.f / l_lo[mt], inv_hi = 1.f / l_hi[mt];
        #pragma unroll
        for (int nt = 0; nt < 8; nt++) {
            int col = h * DH + nt * 8 + 2 * tg;
            size_t r_lo = (size_t)(b * SEQ + q0 + mt * 16 + g) * DM + col;
            size_t r_hi = (size_t)(b * SEQ + q0 + mt * 16 + g + 8) * DM + col;
            *(uint32_t*)&O[r_lo] = f22h2(o[mt][nt][0] * inv_lo, o[mt][nt][1] * inv_lo);
            *(uint32_t*)&O[r_hi] = f22h2(o[mt][nt][2] * inv_hi, o[mt][nt][3] * inv_hi);
        }
    }
}

// ---------------- launch ----------------
extern "C" void kernel_launch(void* const* d_in, const int* in_sizes, int n_in,
                              void* d_out, int out_size)
{
    const float* query  = (const float*)d_in[0];
    const float* key_in = (const float*)d_in[1];
    const float* value  = (const float*)d_in[2];
    const float* Wq  = (const float*)d_in[3];
    const float* bq  = (const float*)d_in[4];
    const float* Wk  = (const float*)d_in[5];
    const float* bk  = (const float*)d_in[6];
    const float* Wv  = (const float*)d_in[7];
    const float* bv  = (const float*)d_in[8];
    const float* Wo  = (const float*)d_in[9];
    const float* bo  = (const float*)d_in[10];
    const float* Ws1 = (const float*)d_in[11];
    const float* bs1 = (const float*)d_in[12];
    const float* Ws2 = (const float*)d_in[13];
    const float* bs2 = (const float*)d_in[14];
    const float* Wc1 = (const float*)d_in[15];
    const float* bc1 = (const float*)d_in[16];
    const float* Wc2 = (const float*)d_in[17];
    const float* bc2 = (const float*)d_in[18];

    __half *pQ, *pK, *pVV, *pVC, *pH, *pVD, *pAO, *pIN, *pWT, *pWVB;
    float *pPART, *pHIDP, *pCWP;
    cudaGetSymbolAddress((void**)&pQ,    g_Qh);
    cudaGetSymbolAddress((void**)&pK,    g_Kh);
    cudaGetSymbolAddress((void**)&pVV,   g_VVh);
    cudaGetSymbolAddress((void**)&pVC,   g_VCh);
    cudaGetSymbolAddress((void**)&pH,    g_Hh);
    cudaGetSymbolAddress((void**)&pVD,   g_VDh);
    cudaGetSymbolAddress((void**)&pAO,   g_AOh);
    cudaGetSymbolAddress((void**)&pIN,   g_INh);
    cudaGetSymbolAddress((void**)&pWT,   g_WTh);
    cudaGetSymbolAddress((void**)&pWVB,  g_WVBh);
    cudaGetSymbolAddress((void**)&pPART, g_PART);
    cudaGetSymbolAddress((void**)&pHIDP, g_HIDP);
    cudaGetSymbolAddress((void**)&pCWP,  g_CWP);

    cudaFuncSetAttribute(proj3,             cudaFuncAttributeMaxDynamicSharedMemorySize, SMEM_GEMM);
    cudaFuncSetAttribute(projVC,            cudaFuncAttributeMaxDynamicSharedMemorySize, SMEM_GEMM);
    cudaFuncSetAttribute((tgemm<2,false>),  cudaFuncAttributeMaxDynamicSharedMemorySize, SMEM_GEMM);
    cudaFuncSetAttribute((tgemm<3,false>),  cudaFuncAttributeMaxDynamicSharedMemorySize, SMEM_GEMM);
    cudaFuncSetAttribute((tgemm<0,true>),   cudaFuncAttributeMaxDynamicSharedMemorySize, SMEM_GEMM);
    cudaFuncSetAttribute(attn_kernel,       cudaFuncAttributeMaxDynamicSharedMemorySize, SMEM_ATTN);

    // fork-join side stream (created per call; kernel_launch is invoked only a
    // few times total — correctness + capture — so leaking these is harmless
    // and avoids destroying resources that are still referenced by capture)
    cudaStream_t s1;
    cudaStreamCreateWithFlags(&s1, cudaStreamNonBlocking);
    cudaEvent_t e_fork, e_join;
    cudaEventCreateWithFlags(&e_fork, cudaEventDisableTiming);
    cudaEventCreateWithFlags(&e_join, cudaEventDisableTiming);

    dim3 g512(DM / 128, MROWS / 128);   // (4, 64)
    dim3 g256(HID / 128, MROWS / 128);  // (2, 64)

    // 0) combined prep on main stream
    prep_all<<<13632, 256>>>(Wq, Wk, Wv, Wo, Ws1, Ws2, query, key_in, value,
                             pWT, pIN, pPART);
    cudaEventRecord(e_fork, 0);

    // side stream: gate chain + VC projection (independent of proj3/S1)
    cudaStreamWaitEvent(s1, e_fork, 0);
    gate1_kernel<<<dim3(Bn, 8), 256, 0, s1>>>(pPART, Wc1, pHIDP);
    gate2_kernel<<<dim3(Bn, 4), 256, 0, s1>>>(pHIDP, bc1, Wc2, pCWP);
    scale_wv_kernel<<<dim3(DM * DM / 2048, Bn), 256, 0, s1>>>(pWT + WT_V, pCWP, bc2, pWVB);
    projVC<<<g512, 256, SMEM_GEMM, s1>>>(pIN, pWVB, bv, pVC);
    cudaEventRecord(e_join, s1);

    // main stream: Q/K/VV projections then S1 (needs only VV)
    proj3<<<dim3(DM / 128, MROWS / 128, 3), 256, SMEM_GEMM>>>(
        pIN, pWT, bq, bk, bv, pQ, pK, pVV);
    tgemm<2,false><<<g256, 256, SMEM_GEMM>>>(pVV, pWT + WT_S1, bs1, pH, DM, HID, nullptr, nullptr);

    // join: S2 needs VC
    cudaStreamWaitEvent(0, e_join, 0);

    // v_dual = VV * sigmoid(H @ Ws2 + bs2) + VC
    tgemm<3,false><<<g512, 256, SMEM_GEMM>>>(pH, pWT + WT_S2, bs2, pVD, HID, DM, pVV, pVC);

    // attention
    attn_kernel<<<dim3(SEQ / 256, NH, Bn), 256, SMEM_ATTN>>>(pQ, pK, pVD, pAO);

    // output projection (fp32 out)
    tgemm<0,true><<<g512, 256, SMEM_GEMM>>>(pAO, pWT + WT_O, bo, (float*)d_out, DM, DM, nullptr, nullptr);
}

// round 17
// speedup vs baseline: 1.0266x; 1.0266x over previous
#include <cuda_runtime.h>
#include <cuda_fp16.h>
#include <math.h>
#include <cstdint>

#define Bn   8
#define SEQ  1024
#define DM   512
#define HID  256
#define NH   8
#define DH   64
#define MROWS (Bn*SEQ)

// ---------------- scratch (device globals; no allocation) ----------------
__device__ __half g_Qh [MROWS*DM];
__device__ __half g_Kh [MROWS*DM];
__device__ __half g_VVh[MROWS*DM];
__device__ __half g_VCh[MROWS*DM];
__device__ __half g_Hh [MROWS*HID];
__device__ __half g_VDh[MROWS*DM];
__device__ __half g_AOh[MROWS*DM];
__device__ __half g_INh[3*MROWS*DM];            // half copies of query,key_in,value
__device__ float  g_PART[Bn*8*DM];
__device__ float  g_HIDP[Bn*8*HID];
__device__ float  g_CWP[Bn*4*DM];
__device__ __half g_WTh[4*DM*DM + 2*DM*HID];    // transposed half weights
__device__ __half g_WVBh[Bn*DM*DM];             // per-batch channel-scaled Wv

#define WT_Q  0
#define WT_K  (DM*DM)
#define WT_V  (2*DM*DM)
#define WT_O  (3*DM*DM)
#define WT_S1 (4*DM*DM)
#define WT_S2 (4*DM*DM + DM*HID)

// ---------------- helpers ----------------
__device__ __forceinline__ uint32_t f22h2(float lo, float hi) {
    uint32_t u; asm("cvt.rn.f16x2.f32 %0, %1, %2;" : "=r"(u) : "f"(hi), "f"(lo)); return u;
}
__device__ __forceinline__ void mma_f16(float* c, const uint32_t* a, uint32_t b0, uint32_t b1) {
    asm volatile("mma.sync.aligned.m16n8k16.row.col.f32.f16.f16.f32 "
        "{%0,%1,%2,%3}, {%4,%5,%6,%7}, {%8,%9}, {%0,%1,%2,%3};"
        : "+f"(c[0]), "+f"(c[1]), "+f"(c[2]), "+f"(c[3])
        : "r"(a[0]), "r"(a[1]), "r"(a[2]), "r"(a[3]), "r"(b0), "r"(b1));
}
__device__ __forceinline__ void ldsm_x4_t(uint32_t& r0, uint32_t& r1, uint32_t& r2, uint32_t& r3,
                                          uint32_t addr) {
    asm volatile("ldmatrix.sync.aligned.m8n8.x4.trans.shared.b16 {%0,%1,%2,%3}, [%4];"
        : "=r"(r0), "=r"(r1), "=r"(r2), "=r"(r3) : "r"(addr));
}
__device__ __forceinline__ uint32_t smem_u32(const void* p) {
    uint32_t a;
    asm("{ .reg .u64 t; cvta.to.shared.u64 t, %1; cvt.u32.u64 %0, t; }" : "=r"(a) : "l"(p));
    return a;
}
__device__ __forceinline__ void cpa16(uint32_t dst, const void* src) {
    asm volatile("cp.async.cg.shared.global [%0], [%1], 16;" :: "r"(dst), "l"(src));
}
#define CP_COMMIT() asm volatile("cp.async.commit_group;" ::: "memory")
#define CP_WAIT1()  asm volatile("cp.async.wait_group 1;" ::: "memory")
#define CP_WAIT0()  asm volatile("cp.async.wait_group 0;" ::: "memory")

// ---------------- prep_all: weight transpose + input cvt + partial means, ONE launch
__global__ void prep_all(const float* __restrict__ Wq, const float* __restrict__ Wk,
                         const float* __restrict__ Wv, const float* __restrict__ Wo,
                         const float* __restrict__ Ws1, const float* __restrict__ Ws2,
                         const float* __restrict__ query, const float* __restrict__ key_in,
                         const float* __restrict__ value,
                         __half* __restrict__ WT, __half* __restrict__ INh,
                         float* __restrict__ part)
{
    int bid = blockIdx.x;
    int t = threadIdx.x;                  // 256

    if (bid < 1280) {
        const float* in; __half* out; int R, C, tb;
        if      (bid < 256)  { in = Wq;  out = WT + WT_Q;  R = DM; C = DM;  tb = bid; }
        else if (bid < 512)  { in = Wk;  out = WT + WT_K;  R = DM; C = DM;  tb = bid - 256; }
        else if (bid < 768)  { in = Wv;  out = WT + WT_V;  R = DM; C = DM;  tb = bid - 512; }
        else if (bid < 1024) { in = Wo;  out = WT + WT_O;  R = DM; C = DM;  tb = bid - 768; }
        else if (bid < 1152) { in = Ws1; out = WT + WT_S1; R = DM; C = HID; tb = bid - 1024; }
        else                 { in = Ws2; out = WT + WT_S2; R = HID; C = DM; tb = bid - 1152; }
        int tilesX = C >> 5;
        int bx = (tb % tilesX) * 32, by = (tb / tilesX) * 32;
        __shared__ float tile[32][33];
        int tx = t & 31, ty = t >> 5;     // (32, 8)
        #pragma unroll
        for (int i = 0; i < 32; i += 8)
            tile[ty + i][tx] = in[(size_t)(by + ty + i) * C + bx + tx];
        __syncthreads();
        #pragma unroll
        for (int i = 0; i < 32; i += 8)
            out[(size_t)(bx + ty + i) * R + by + tx] = __float2half_rn(tile[tx][ty + i]);
    } else if (bid < 13568) {
        int i  = bid - 1280;
        int y  = i >> 12;                 // 0..2
        int x  = i & 4095;
        const float* src = (y == 0) ? query : (y == 1) ? key_in : value;
        size_t i4 = ((size_t)x * 256 + t) * 4;
        float4 f = *(const float4*)&src[i4];
        uint2 o;
        o.x = f22h2(f.x, f.y);
        o.y = f22h2(f.z, f.w);
        *(uint2*)(INh + (size_t)y * MROWS * DM + i4) = o;
    } else {
        int i = bid - 13568;              // 0..63
        int b = i >> 3, s = i & 7;
        const float* vb = value + ((size_t)b * SEQ + s * 128) * DM;
        #pragma unroll
        for (int d = t; d < DM; d += 256) {
            float acc = 0.f;
            #pragma unroll 8
            for (int n = 0; n < 128; n++) acc += vb[(size_t)n * DM + d];
            part[(b * 8 + s) * DM + d] = acc;
        }
    }
}

// ---------------- channel gate, split-K wide-parallel ----------------
__global__ void gate1_kernel(const float* __restrict__ part, const float* __restrict__ Wc1,
                             float* __restrict__ hidp)
{
    int b = blockIdx.x, sl = blockIdx.y;   // (8, 8)
    int t = threadIdx.x;                   // 256
    __shared__ float ps[64];
    if (t < 64) {
        int d = sl * 64 + t;
        float s = 0.f;
        #pragma unroll
        for (int k = 0; k < 8; k++) s += part[(b * 8 + k) * DM + d];
        ps[t] = s * (1.0f / SEQ);
    }
    __syncthreads();
    float acc = 0.f;
    #pragma unroll
    for (int dd = 0; dd < 64; dd++)
        acc += ps[dd] * Wc1[(sl * 64 + dd) * HID + t];
    hidp[(b * 8 + sl) * HID + t] = acc;
}

__global__ void gate2_kernel(const float* __restrict__ hidp, const float* __restrict__ bc1,
                             const float* __restrict__ Wc2, float* __restrict__ cwp)
{
    int b = blockIdx.x, sl = blockIdx.y;   // (8, 4)
    int t = threadIdx.x;                   // 256
    __shared__ float hs[64];
    if (t < 64) {
        int h = sl * 64 + t;
        float s = bc1[h];
        #pragma unroll
        for (int k = 0; k < 8; k++) s += hidp[(b * 8 + k) * HID + h];
        hs[t] = fmaxf(s, 0.f);
    }
    __syncthreads();
    #pragma unroll
    for (int rep = 0; rep < 2; rep++) {
        int d = rep * 256 + t;
        float acc = 0.f;
        #pragma unroll
        for (int hh = 0; hh < 64; hh++)
            acc += hs[hh] * Wc2[(sl * 64 + hh) * DM + d];
        cwp[(b * 4 + sl) * DM + d] = acc;
    }
}

// ---------------- per-batch scaled Wv (half), sigmoid reduce folded in ----------------
__global__ void scale_wv_kernel(const __half* __restrict__ WTV, const float* __restrict__ cwp,
                                const float* __restrict__ bc2, __half* __restrict__ WVB)
{
    int b = blockIdx.y;
    size_t j0 = ((size_t)blockIdx.x * 256 + threadIdx.x) * 8;
    int k = (int)(j0 & (DM - 1));
    float cw[8];
    #pragma unroll
    for (int i = 0; i < 8; i += 4) {
        float4 s4 = *(const float4*)&bc2[k + i];
        #pragma unroll
        for (int sl = 0; sl < 4; sl++) {
            float4 p = *(const float4*)&cwp[(b * 4 + sl) * DM + k + i];
            s4.x += p.x; s4.y += p.y; s4.z += p.z; s4.w += p.w;
        }
        cw[i]   = 1.f / (1.f + __expf(-s4.x));
        cw[i+1] = 1.f / (1.f + __expf(-s4.y));
        cw[i+2] = 1.f / (1.f + __expf(-s4.z));
        cw[i+3] = 1.f / (1.f + __expf(-s4.w));
    }
    uint4 w = *(const uint4*)&WTV[j0];
    uint32_t r[4];
    const uint32_t* ww = (const uint32_t*)&w;
    #pragma unroll
    for (int i = 0; i < 4; i++) {
        __half2 h = *(__half2*)&ww[i];
        float lo = __low2float(h) * cw[2 * i];
        float hi = __high2float(h) * cw[2 * i + 1];
        r[i] = f22h2(lo, hi);
    }
    *(uint4*)&WVB[(size_t)b * DM * DM + j0] = *(uint4*)r;
}

// ---------------- fp16 mma GEMM, K-chunk 64 halfs, 3-stage cp.async ring
#define PITCHW 36
#define TWRD  (128*PITCHW)
#define STGW  (2*TWRD)
#define NSTG  3
#define SMEM_GEMM (NSTG*STGW*4)        // 110592 B

template<int MODE, bool FLOATOUT, bool QSCALE>
__device__ __forceinline__
void gemm_body(const __half* __restrict__ A, const __half* __restrict__ B,
               const float* __restrict__ bias, void* __restrict__ Cv,
               int Kd, int Nd,
               const __half* __restrict__ E1, const __half* __restrict__ E2,
               int m0, int n0)
{
    extern __shared__ __align__(16) uint32_t usm[];
    const uint32_t sb = smem_u32(usm);
    const int t    = threadIdx.x;
    const int lane = t & 31;
    const int wid  = t >> 5;
    const int g    = lane >> 2;
    const int tg   = lane & 3;
    const int wm   = wid & 3;
    const int wn   = wid >> 2;
    const int NK   = Kd / 64;

    float acc[2][8][4];
    #pragma unroll
    for (int mt = 0; mt < 2; mt++)
        #pragma unroll
        for (int nt = 0; nt < 8; nt++)
            #pragma unroll
            for (int j = 0; j < 4; j++) acc[mt][nt][j] = 0.f;

    auto issue = [&](int kc) {
        if (kc < NK) {
            const int k0 = kc * 64;
            const uint32_t ab = sb + (kc % NSTG) * (STGW * 4);
            #pragma unroll
            for (int i = 0; i < 4; i++) {
                int idx = t + i * 256;
                int row = idx >> 3, q = idx & 7;
                uint32_t soff = (row * PITCHW + q * 4) * 4;
                cpa16(ab + soff,              &A[(size_t)(m0 + row) * Kd + k0 + q * 8]);
                cpa16(ab + TWRD * 4 + soff,   &B[(size_t)(n0 + row) * Kd + k0 + q * 8]);
            }
        }
        CP_COMMIT();
    };

    issue(0); issue(1);

    for (int kc = 0; kc < NK; kc++) {
        CP_WAIT1();
        __syncthreads();
        issue(kc + 2);

        const uint32_t* Aw = usm + (kc % NSTG) * STGW;
        const uint32_t* Bw = Aw + TWRD;
        #pragma unroll
        for (int ks = 0; ks < 4; ks++) {
            const int c0 = ks * 8 + tg;
            uint32_t af[2][4];
            #pragma unroll
            for (int mt = 0; mt < 2; mt++) {
                int r0 = wm * 32 + mt * 16 + g;
                af[mt][0] = Aw[r0 * PITCHW + c0];
                af[mt][1] = Aw[(r0 + 8) * PITCHW + c0];
                af[mt][2] = Aw[r0 * PITCHW + c0 + 4];
                af[mt][3] = Aw[(r0 + 8) * PITCHW + c0 + 4];
            }
            #pragma unroll
            for (int nt = 0; nt < 8; nt++) {
                int nn = wn * 64 + nt * 8 + g;
                uint32_t b0 = Bw[nn * PITCHW + c0];
                uint32_t b1 = Bw[nn * PITCHW + c0 + 4];
                mma_f16(acc[0][nt], af[0], b0, b1);
                mma_f16(acc[1][nt], af[1], b0, b1);
            }
        }
    }

    #pragma unroll
    for (int mt = 0; mt < 2; mt++) {
        int r_lo = m0 + wm * 32 + mt * 16 + g;
        int r_hi = r_lo + 8;
        #pragma unroll
        for (int nt = 0; nt < 8; nt++) {
            int col = n0 + wn * 64 + nt * 8 + 2 * tg;
            float bx = bias[col], by = bias[col + 1];
            float v0 = acc[mt][nt][0] + bx;
            float v1 = acc[mt][nt][1] + by;
            float v2 = acc[mt][nt][2] + bx;
            float v3 = acc[mt][nt][3] + by;
            if (MODE == 2) {
                v0 = fmaxf(v0, 0.f); v1 = fmaxf(v1, 0.f);
                v2 = fmaxf(v2, 0.f); v3 = fmaxf(v3, 0.f);
            }
            if (MODE == 3) {
                size_t i_lo = (size_t)r_lo * Nd + col;
                size_t i_hi = (size_t)r_hi * Nd + col;
                float2 e1l = __half22float2(*(const __half2*)&E1[i_lo]);
                float2 e2l = __half22float2(*(const __half2*)&E2[i_lo]);
                float2 e1h = __half22float2(*(const __half2*)&E1[i_hi]);
                float2 e2h = __half22float2(*(const __half2*)&E2[i_hi]);
                v0 = e1l.x / (1.f + __expf(-v0)) + e2l.x;
                v1 = e1l.y / (1.f + __expf(-v1)) + e2l.y;
                v2 = e1h.x / (1.f + __expf(-v2)) + e2h.x;
                v3 = e1h.y / (1.f + __expf(-v3)) + e2h.y;
            }
            if (QSCALE) { v0 *= 0.125f; v1 *= 0.125f; v2 *= 0.125f; v3 *= 0.125f; }
            if (FLOATOUT) {
                float* C = (float*)Cv;
                *(float2*)&C[(size_t)r_lo * Nd + col] = make_float2(v0, v1);
                *(float2*)&C[(size_t)r_hi * Nd + col] = make_float2(v2, v3);
            } else {
                __half* C = (__half*)Cv;
                *(uint32_t*)&C[(size_t)r_lo * Nd + col] = f22h2(v0, v1);
                *(uint32_t*)&C[(size_t)r_hi * Nd + col] = f22h2(v2, v3);
            }
        }
    }
}

template<int MODE, bool FLOATOUT>
__global__ __launch_bounds__(256, 2)
void tgemm(const __half* __restrict__ A, const __half* __restrict__ B,
           const float* __restrict__ bias, void* __restrict__ C,
           int Kd, int Nd,
           const __half* __restrict__ E1, const __half* __restrict__ E2)
{
    gemm_body<MODE, FLOATOUT, false>(A, B, bias, C, Kd, Nd, E1, E2,
                                     blockIdx.y * 128, blockIdx.x * 128);
}

// Q/K/VV projections (Q pre-scaled by 0.125); VC split off for stream overlap
__global__ __launch_bounds__(256, 2)
void proj3(const __half* __restrict__ INh, const __half* __restrict__ WTb,
           const float* __restrict__ bq, const float* __restrict__ bk,
           const float* __restrict__ bv,
           __half* __restrict__ oQ, __half* __restrict__ oK,
           __half* __restrict__ oVV)
{
    const int z = blockIdx.z;
    const int m0 = blockIdx.y * 128, n0 = blockIdx.x * 128;
    const __half* qh = INh;
    const __half* kh = INh + (size_t)MROWS * DM;
    const __half* vh = INh + (size_t)2 * MROWS * DM;
    if (z == 0)
        gemm_body<0, false, true >(qh, WTb + WT_Q, bq, oQ,  DM, DM, nullptr, nullptr, m0, n0);
    else if (z == 1)
        gemm_body<0, false, false>(kh, WTb + WT_K, bk, oK,  DM, DM, nullptr, nullptr, m0, n0);
    else
        gemm_body<0, false, false>(vh, WTb + WT_V, bv, oVV, DM, DM, nullptr, nullptr, m0, n0);
}

__global__ __launch_bounds__(256, 2)
void projVC(const __half* __restrict__ INh, const __half* __restrict__ WVB,
            const float* __restrict__ bv, __half* __restrict__ oVC)
{
    const int m0 = blockIdx.y * 128, n0 = blockIdx.x * 128;
    const int bb = blockIdx.y >> 3;
    const __half* vh = INh + (size_t)2 * MROWS * DM;
    gemm_body<0, false, false>(vh, WVB + (size_t)bb * DM * DM, bv, oVC, DM, DM,
                               nullptr, nullptr, m0, n0);
}

// ---------------- flash attention: fp16 mma, 256-query CTAs (warp owns 32 q)
#define KVPW   36
#define KVTOK  64
#define ASTGW  (2*KVTOK*KVPW)           // 4608 words per stage (K+V)
#define SMEM_ATTN (2*ASTGW*4)           // 36864 B

__global__ __launch_bounds__(256, 1)
void attn_kernel(const __half* __restrict__ Q, const __half* __restrict__ Kp,
                 const __half* __restrict__ V, __half* __restrict__ O)
{
    extern __shared__ __align__(16) uint32_t usm[];
    const uint32_t sb = smem_u32(usm);

    const int qt = blockIdx.x;           // 4 tiles of 256 queries
    const int h  = blockIdx.y;
    const int b  = blockIdx.z;
    const int t  = threadIdx.x;
    const int lane = t & 31;
    const int wid  = t >> 5;
    const int g  = lane >> 2;
    const int tg = lane & 3;
    const int q0 = qt * 256 + wid * 32;  // warp owns 32 queries (2 x m16)

    uint32_t aq[2][4][4];
    #pragma unroll
    for (int mt = 0; mt < 2; mt++) {
        const __half* Qb = Q + ((size_t)(b * SEQ + q0 + mt * 16)) * DM + h * DH;
        #pragma unroll
        for (int ks = 0; ks < 4; ks++) {
            int c0 = ks * 16 + 2 * tg;
            aq[mt][ks][0] = *(const uint32_t*)&Qb[(size_t)g * DM + c0];
            aq[mt][ks][1] = *(const uint32_t*)&Qb[(size_t)(g + 8) * DM + c0];
            aq[mt][ks][2] = *(const uint32_t*)&Qb[(size_t)g * DM + c0 + 8];
            aq[mt][ks][3] = *(const uint32_t*)&Qb[(size_t)(g + 8) * DM + c0 + 8];
        }
    }

    float o[2][8][4];
    #pragma unroll
    for (int mt = 0; mt < 2; mt++)
        #pragma unroll
        for (int nt = 0; nt < 8; nt++)
            #pragma unroll
            for (int j = 0; j < 4; j++) o[mt][nt][j] = 0.f;
    float m_lo[2] = {-1e30f, -1e30f}, m_hi[2] = {-1e30f, -1e30f};
    float l_lo[2] = {0.f, 0.f},       l_hi[2] = {0.f, 0.f};

    const int keyoff = lane & 15;
    const int ncoff  = ((lane >> 4) & 1) * 8;

    auto issue = [&](int kt) {
        if (kt < SEQ / KVTOK) {
            const uint32_t ab = sb + (kt & 1) * (ASTGW * 4);
            #pragma unroll
            for (int i = 0; i < 2; i++) {
                int idx = t + i * 256;
                int tok = idx >> 3, q = idx & 7;
                size_t gaddr = ((size_t)(b * SEQ + kt * KVTOK + tok)) * DM + h * DH + q * 8;
                cpa16(ab + (tok * KVPW + q * 4) * 4, &Kp[gaddr]);
                cpa16(ab + (KVTOK * KVPW + tok * KVPW + q * 4) * 4, &V[gaddr]);
            }
        }
        CP_COMMIT();
    };

    issue(0);

    for (int kt = 0; kt < SEQ / KVTOK; kt++) {
        CP_WAIT0();
        __syncthreads();
        issue(kt + 1);

        const uint32_t* Ks = usm + (kt & 1) * ASTGW;
        const uint32_t  vsb = sb + ((kt & 1) * ASTGW + KVTOK * KVPW) * 4;

        float s[2][8][4];
        #pragma unroll
        for (int mt = 0; mt < 2; mt++)
            #pragma unroll
            for (int nt = 0; nt < 8; nt++)
                #pragma unroll
                for (int j = 0; j < 4; j++) s[mt][nt][j] = 0.f;
        #pragma unroll
        for (int ks = 0; ks < 4; ks++) {
            const int c0 = ks * 8 + tg;
            #pragma unroll
            for (int nt = 0; nt < 8; nt++) {
                int key = nt * 8 + g;
                uint32_t b0 = Ks[key * KVPW + c0];
                uint32_t b1 = Ks[key * KVPW + c0 + 4];
                mma_f16(s[0][nt], aq[0][ks], b0, b1);
                mma_f16(s[1][nt], aq[1][ks], b0, b1);
            }
        }

        #pragma unroll
        for (int mt = 0; mt < 2; mt++) {
            float tl = -1e30f, th = -1e30f;
            #pragma unroll
            for (int nt = 0; nt < 8; nt++) {
                tl = fmaxf(tl, fmaxf(s[mt][nt][0], s[mt][nt][1]));
                th = fmaxf(th, fmaxf(s[mt][nt][2], s[mt][nt][3]));
            }
            tl = fmaxf(tl, __shfl_xor_sync(0xffffffffu, tl, 1));
            tl = fmaxf(tl, __shfl_xor_sync(0xffffffffu, tl, 2));
            th = fmaxf(th, __shfl_xor_sync(0xffffffffu, th, 1));
            th = fmaxf(th, __shfl_xor_sync(0xffffffffu, th, 2));
            float mn_l = fmaxf(m_lo[mt], tl), mn_h = fmaxf(m_hi[mt], th);
            float fl = __expf(m_lo[mt] - mn_l), fh = __expf(m_hi[mt] - mn_h);
            m_lo[mt] = mn_l; m_hi[mt] = mn_h;

            float sl = 0.f, sh = 0.f;
            #pragma unroll
            for (int nt = 0; nt < 8; nt++) {
                s[mt][nt][0] = __expf(s[mt][nt][0] - mn_l);
                s[mt][nt][1] = __expf(s[mt][nt][1] - mn_l);
                s[mt][nt][2] = __expf(s[mt][nt][2] - mn_h);
                s[mt][nt][3] = __expf(s[mt][nt][3] - mn_h);
                sl += s[mt][nt][0] + s[mt][nt][1];
                sh += s[mt][nt][2] + s[mt][nt][3];
            }
            sl += __shfl_xor_sync(0xffffffffu, sl, 1);
            sl += __shfl_xor_sync(0xffffffffu, sl, 2);
            sh += __shfl_xor_sync(0xffffffffu, sh, 1);
            sh += __shfl_xor_sync(0xffffffffu, sh, 2);
            l_lo[mt] = l_lo[mt] * fl + sl;
            l_hi[mt] = l_hi[mt] * fh + sh;
            #pragma unroll
            for (int nt = 0; nt < 8; nt++) {
                o[mt][nt][0] *= fl; o[mt][nt][1] *= fl;
                o[mt][nt][2] *= fh; o[mt][nt][3] *= fh;
            }
        }

        #pragma unroll
        for (int kk = 0; kk < 4; kk++) {
            uint32_t pa0[4], pa1[4];
            pa0[0] = f22h2(s[0][2*kk][0],   s[0][2*kk][1]);
            pa0[1] = f22h2(s[0][2*kk][2],   s[0][2*kk][3]);
            pa0[2] = f22h2(s[0][2*kk+1][0], s[0][2*kk+1][1]);
            pa0[3] = f22h2(s[0][2*kk+1][2], s[0][2*kk+1][3]);
            pa1[0] = f22h2(s[1][2*kk][0],   s[1][2*kk][1]);
            pa1[1] = f22h2(s[1][2*kk][2],   s[1][2*kk][3]);
            pa1[2] = f22h2(s[1][2*kk+1][0], s[1][2*kk+1][1]);
            pa1[3] = f22h2(s[1][2*kk+1][2], s[1][2*kk+1][3]);
            #pragma unroll
            for (int np = 0; np < 4; np++) {
                uint32_t addr = vsb + (uint32_t)((16 * kk + keyoff) * (KVPW * 4)
                                               + (np * 16 + ncoff) * 2);
                uint32_t vb0, vb1, vb2, vb3;
                ldsm_x4_t(vb0, vb1, vb2, vb3, addr);
                mma_f16(o[0][2*np],   pa0, vb0, vb1);
                mma_f16(o[0][2*np+1], pa0, vb2, vb3);
                mma_f16(o[1][2*np],   pa1, vb0, vb1);
                mma_f16(o[1][2*np+1], pa1, vb2, vb3);
            }
        }
    }

    #pragma unroll
    for (int mt = 0; mt < 2; mt++) {
        float inv_lo = 1.f / l_lo[mt], inv_hi = 1.f / l_hi[mt];
        #pragma unroll
        for (int nt = 0; nt < 8; nt++) {
            int col = h * DH + nt * 8 + 2 * tg;
            size_t r_lo = (size_t)(b * SEQ + q0 + mt * 16 + g) * DM + col;
            size_t r_hi = (size_t)(b * SEQ + q0 + mt * 16 + g + 8) * DM + col;
            *(uint32_t*)&O[r_lo] = f22h2(o[mt][nt][0] * inv_lo, o[mt][nt][1] * inv_lo);
            *(uint32_t*)&O[r_hi] = f22h2(o[mt][nt][2] * inv_hi, o[mt][nt][3] * inv_hi);
        }
    }
}

// ---------------- launch ----------------
extern "C" void kernel_launch(void* const* d_in, const int* in_sizes, int n_in,
                              void* d_out, int out_size)
{
    const float* query  = (const float*)d_in[0];
    const float* key_in = (const float*)d_in[1];
    const float* value  = (const float*)d_in[2];
    const float* Wq  = (const float*)d_in[3];
    const float* bq  = (const float*)d_in[4];
    const float* Wk  = (const float*)d_in[5];
    const float* bk  = (const float*)d_in[6];
    const float* Wv  = (const float*)d_in[7];
    const float* bv  = (const float*)d_in[8];
    const float* Wo  = (const float*)d_in[9];
    const float* bo  = (const float*)d_in[10];
    const float* Ws1 = (const float*)d_in[11];
    const float* bs1 = (const float*)d_in[12];
    const float* Ws2 = (const float*)d_in[13];
    const float* bs2 = (const float*)d_in[14];
    const float* Wc1 = (const float*)d_in[15];
    const float* bc1 = (const float*)d_in[16];
    const float* Wc2 = (const float*)d_in[17];
    const float* bc2 = (const float*)d_in[18];

    __half *pQ, *pK, *pVV, *pVC, *pH, *pVD, *pAO, *pIN, *pWT, *pWVB;
    float *pPART, *pHIDP, *pCWP;
    cudaGetSymbolAddress((void**)&pQ,    g_Qh);
    cudaGetSymbolAddress((void**)&pK,    g_Kh);
    cudaGetSymbolAddress((void**)&pVV,   g_VVh);
    cudaGetSymbolAddress((void**)&pVC,   g_VCh);
    cudaGetSymbolAddress((void**)&pH,    g_Hh);
    cudaGetSymbolAddress((void**)&pVD,   g_VDh);
    cudaGetSymbolAddress((void**)&pAO,   g_AOh);
    cudaGetSymbolAddress((void**)&pIN,   g_INh);
    cudaGetSymbolAddress((void**)&pWT,   g_WTh);
    cudaGetSymbolAddress((void**)&pWVB,  g_WVBh);
    cudaGetSymbolAddress((void**)&pPART, g_PART);
    cudaGetSymbolAddress((void**)&pHIDP, g_HIDP);
    cudaGetSymbolAddress((void**)&pCWP,  g_CWP);

    cudaFuncSetAttribute(proj3,             cudaFuncAttributeMaxDynamicSharedMemorySize, SMEM_GEMM);
    cudaFuncSetAttribute(projVC,            cudaFuncAttributeMaxDynamicSharedMemorySize, SMEM_GEMM);
    cudaFuncSetAttribute((tgemm<2,false>),  cudaFuncAttributeMaxDynamicSharedMemorySize, SMEM_GEMM);
    cudaFuncSetAttribute((tgemm<3,false>),  cudaFuncAttributeMaxDynamicSharedMemorySize, SMEM_GEMM);
    cudaFuncSetAttribute((tgemm<0,true>),   cudaFuncAttributeMaxDynamicSharedMemorySize, SMEM_GEMM);
    cudaFuncSetAttribute(attn_kernel,       cudaFuncAttributeMaxDynamicSharedMemorySize, SMEM_ATTN);

    // fork-join side stream (created per call; kernel_launch is invoked only a
    // few times total — correctness + capture — so leaking these is harmless
    // and avoids destroying resources that are still referenced by capture)
    cudaStream_t s1;
    cudaStreamCreateWithFlags(&s1, cudaStreamNonBlocking);
    cudaEvent_t e_fork, e_join;
    cudaEventCreateWithFlags(&e_fork, cudaEventDisableTiming);
    cudaEventCreateWithFlags(&e_join, cudaEventDisableTiming);

    dim3 g512(DM / 128, MROWS / 128);   // (4, 64)
    dim3 g256(HID / 128, MROWS / 128);  // (2, 64)

    // 0) combined prep on main stream
    prep_all<<<13632, 256>>>(Wq, Wk, Wv, Wo, Ws1, Ws2, query, key_in, value,
                             pWT, pIN, pPART);
    cudaEventRecord(e_fork, 0);

    // side stream: gate chain + VC projection (independent of proj3/S1)
    cudaStreamWaitEvent(s1, e_fork, 0);
    gate1_kernel<<<dim3(Bn, 8), 256, 0, s1>>>(pPART, Wc1, pHIDP);
    gate2_kernel<<<dim3(Bn, 4), 256, 0, s1>>>(pHIDP, bc1, Wc2, pCWP);
    scale_wv_kernel<<<dim3(DM * DM / 2048, Bn), 256, 0, s1>>>(pWT + WT_V, pCWP, bc2, pWVB);
    projVC<<<g512, 256, SMEM_GEMM, s1>>>(pIN, pWVB, bv, pVC);
    cudaEventRecord(e_join, s1);

    // main stream: Q/K/VV projections then S1 (needs only VV)
    proj3<<<dim3(DM / 128, MROWS / 128, 3), 256, SMEM_GEMM>>>(
        pIN, pWT, bq, bk, bv, pQ, pK, pVV);
    tgemm<2,false><<<g256, 256, SMEM_GEMM>>>(pVV, pWT + WT_S1, bs1, pH, DM, HID, nullptr, nullptr);

    // join: S2 needs VC
    cudaStreamWaitEvent(0, e_join, 0);

    // v_dual = VV * sigmoid(H @ Ws2 + bs2) + VC
    tgemm<3,false><<<g512, 256, SMEM_GEMM>>>(pH, pWT + WT_S2, bs2, pVD, HID, DM, pVV, pVC);

    // attention
    attn_kernel<<<dim3(SEQ / 256, NH, Bn), 256, SMEM_ATTN>>>(pQ, pK, pVD, pAO);

    // output projection (fp32 out)
    tgemm<0,true><<<g512, 256, SMEM_GEMM>>>(pAO, pWT + WT_O, bo, (float*)d_out, DM, DM, nullptr, nullptr);
}